// round 13
// baseline (speedup 1.0000x reference)
#include <cuda_runtime.h>
#include <cstdint>
#define DI __device__ __forceinline__

__device__ float g_p [8192*128];
__device__ float g_v [8192*128];
__device__ float g_P1[8192*128];
__device__ float g_V1[8192*128];
__device__ float g_Wfp[128*128];
__device__ float g_Wfv[128*128];
__device__ float g_biasF[2*128];
// tf32 fragment packs for pv prologue (k32 slabs, stride 36)
__device__ __align__(16) unsigned g_Wpf [4*4608];
__device__ __align__(16) unsigned g_Wfpf[4*4608];
__device__ __align__(16) unsigned g_Wvf [4*4608];
__device__ __align__(16) unsigned g_Wfvf[4*4608];
// fp16 fragment packs for main kernel (k64 slabs, stride 36)
__device__ __align__(16) unsigned g_W1h[4*4608];   // W1c|W1d rows 256..511
__device__ __align__(16) unsigned g_W2h[2*4608];

DI unsigned f2tf(float x){ unsigned r; asm("cvt.rna.tf32.f32 %0, %1;":"=r"(r):"f"(x)); return r; }
DI unsigned pk2(float lo, float hi){
    unsigned r;
    asm("cvt.rn.f16x2.f32 %0, %1, %2;" : "=r"(r) : "f"(hi), "f"(lo));
    return r;
}
DI void mma8(float* c, unsigned a0,unsigned a1,unsigned a2,unsigned a3,unsigned b0,unsigned b1){
    asm volatile("mma.sync.aligned.m16n8k8.row.col.f32.tf32.tf32.f32 "
        "{%0,%1,%2,%3},{%4,%5,%6,%7},{%8,%9},{%0,%1,%2,%3};\n"
        :"+f"(c[0]),"+f"(c[1]),"+f"(c[2]),"+f"(c[3])
        :"r"(a0),"r"(a1),"r"(a2),"r"(a3),"r"(b0),"r"(b1)); }
DI void mma16(float* c, unsigned a0,unsigned a1,unsigned a2,unsigned a3,unsigned b0,unsigned b1){
    asm volatile("mma.sync.aligned.m16n8k16.row.col.f32.f16.f16.f32 "
        "{%0,%1,%2,%3},{%4,%5,%6,%7},{%8,%9},{%0,%1,%2,%3};\n"
        :"+f"(c[0]),"+f"(c[1]),"+f"(c[2]),"+f"(c[3])
        :"r"(a0),"r"(a1),"r"(a2),"r"(a3),"r"(b0),"r"(b1)); }
DI uint32_t s2u(const void* p){ uint32_t a; asm("{ .reg .u64 t; cvta.to.shared.u64 t, %1; cvt.u32.u64 %0, t; }":"=r"(a):"l"(p)); return a; }

// ---- bulk async copy (UBLKCP) + mbarrier ----
DI void bulkcp(uint32_t dst, const void* src, uint32_t bytes, uint32_t mbar){
    asm volatile("cp.async.bulk.shared::cta.global.mbarrier::complete_tx::bytes [%0], [%1], %2, [%3];"
                 :: "r"(dst), "l"(src), "r"(bytes), "r"(mbar) : "memory");
}
#define MBAR_INIT(a,n)   asm volatile("mbarrier.init.shared.b64 [%0], %1;"::"r"(a),"r"(n):"memory")
#define MBAR_EXPECT(a,b) asm volatile("mbarrier.arrive.expect_tx.shared.b64 _, [%0], %1;"::"r"(a),"r"(b):"memory")
DI void mbwait(uint32_t mb, uint32_t par){
    uint32_t done;
    asm volatile("{\n\t.reg .pred p;\n\tmbarrier.try_wait.parity.acquire.cta.shared::cta.b64 p, [%1], %2;\n\tselp.b32 %0,1,0,p;\n\t}"
        :"=r"(done):"r"(mb),"r"(par):"memory");
    if(!done) asm volatile("{\n\t.reg .pred P1;\n\tWL_%=:\n\t"
        "mbarrier.try_wait.parity.acquire.cta.shared::cta.b64 P1, [%0], %1, 0x989680;\n\t"
        "@P1 bra.uni WD_%=;\n\tbra.uni WL_%=;\n\tWD_%=:\n\t}"::"r"(mb),"r"(par):"memory");
}

// tf32 slab mma for pv kernel (unchanged, proven)
DI void mma_slab(float (*acc)[16][4], const unsigned* Ab, const unsigned* Wb, int lane){
#pragma unroll
    for(int ks=0; ks<4; ks++){
        unsigned a[2][4];
#pragma unroll
        for(int mi=0; mi<2; mi++){
            int c0 = ks*8 + mi*2;
            a[mi][0]=Ab[(c0+0)*32+lane]; a[mi][1]=Ab[(c0+1)*32+lane];
            a[mi][2]=Ab[(c0+4)*32+lane]; a[mi][3]=Ab[(c0+5)*32+lane];
        }
        const uint4* bb = (const uint4*)(Wb + (ks*32+lane)*36);
#pragma unroll
        for(int jj=0; jj<8; jj++){
            uint4 b = bb[jj];
            mma8(acc[0][2*jj],  a[0][0],a[0][1],a[0][2],a[0][3],b.x,b.y);
            mma8(acc[1][2*jj],  a[1][0],a[1][1],a[1][2],a[1][3],b.x,b.y);
            mma8(acc[0][2*jj+1],a[0][0],a[0][1],a[0][2],a[0][3],b.z,b.w);
            mma8(acc[1][2*jj+1],a[1][0],a[1][1],a[1][2],a[1][3],b.z,b.w);
        }
    }
}

__global__ __launch_bounds__(256) void prep_kernel(
    const float* __restrict__ Wp, const float* __restrict__ bp,
    const float* __restrict__ Wv, const float* __restrict__ bv,
    const float* __restrict__ W1){
    __shared__ float Wc_s[32*128];
    __shared__ float Wr_s[16*128];
    int cb = blockIdx.x, isv = cb>=8, rb = (cb&7)*16;
    const float* Wx  = isv? Wv: Wp;
    const float* W1x = W1 + (isv? 128*128: 0);
    float* outW = isv? g_Wfv: g_Wfp;
    int t = threadIdx.x;
    for(int i=t; i<16*128; i+=256) Wr_s[i] = Wx[(rb+(i>>7))*128 + (i&127)];
    float acc[8];
#pragma unroll
    for(int ii=0; ii<8; ii++) acc[ii]=0.f;
    int j = t&127, ih = (t>>7)*8;
    for(int kc=0; kc<4; kc++){
        __syncthreads();
        for(int i=t; i<32*128; i+=256) Wc_s[i] = W1x[(kc*32+(i>>7))*128 + (i&127)];
        __syncthreads();
        for(int k=0; k<32; k++){
            float b = Wc_s[k*128+j];
#pragma unroll
            for(int ii=0; ii<8; ii++) acc[ii] += Wr_s[(ih+ii)*128 + kc*32+k]*b;
        }
    }
#pragma unroll
    for(int ii=0; ii<8; ii++) outW[(rb+ih+ii)*128 + j] = acc[ii];
    if((cb&7)==0 && t<128){
        const float* bx = isv? bv: bp;
        float s=0.f;
        for(int k=0;k<128;k++) s += bx[k]*W1x[k*128+t];
        g_biasF[isv*128+t] = s;
    }
}

__global__ __launch_bounds__(128) void pack_kernel(
    const float* __restrict__ Wp, const float* __restrict__ Wv){
    int sid = blockIdx.x;
    const float* src; unsigned* dst;
    if      (sid<4) { src = Wp + sid*32*128;          dst = g_Wpf  + sid*4608; }
    else if (sid<8) { src = g_Wfp + (sid-4)*32*128;   dst = g_Wfpf + (sid-4)*4608; }
    else if (sid<12){ src = Wv + (sid-8)*32*128;      dst = g_Wvf  + (sid-8)*4608; }
    else            { src = g_Wfv + (sid-12)*32*128;  dst = g_Wfvf + (sid-12)*4608; }
    int t=threadIdx.x, lane=t&31, ks=t>>5, gid=lane>>2, t4=lane&3;
#pragma unroll
    for(int j=0;j<16;j++)
#pragma unroll
        for(int r=0;r<2;r++)
            dst[(ks*32+lane)*36 + 2*j + r] = f2tf(src[(ks*8+t4+r*4)*128 + j*8 + gid]);
}

// fp16 fragment pack for main-kernel weights. grid 6 x 128.
__global__ __launch_bounds__(128) void pack16_kernel(
    const float* __restrict__ W1, const float* __restrict__ W2){
    int sid = blockIdx.x;
    const float* src; unsigned* dst;
    if(sid<4){ src = W1 + (256 + sid*64)*128; dst = g_W1h + sid*4608; }
    else     { src = W2 + (sid-4)*64*128;     dst = g_W2h + (sid-4)*4608; }
    int t=threadIdx.x, lane=t&31, ks=t>>5, gid=lane>>2, t4=lane&3;
#pragma unroll
    for(int j=0;j<16;j++)
#pragma unroll
        for(int r=0;r<2;r++){
            int k0 = ks*16 + 2*t4 + 8*r;
            dst[(ks*32+lane)*36 + 2*j + r] =
                pk2(src[k0*128 + 8*j + gid], src[(k0+1)*128 + 8*j + gid]);
        }
}

// pv: bulk-copy version (R12, passing)
__global__ __launch_bounds__(256) void pv_kernel(
    const float* __restrict__ price, const float* __restrict__ liquid,
    const float* __restrict__ bp, const float* __restrict__ bv){
    extern __shared__ float smpv[];
    unsigned* W_s = (unsigned*)smpv;
    unsigned* A_f = (unsigned*)smpv + 9216;
    float* bias_s = smpv + 13312;
    int cb=blockIdx.x, isv=cb>=64, rb=(cb&63)*128;
    const float* in = (isv? liquid: price) + (size_t)rb*128;
    const unsigned* pA = isv? g_Wvf : g_Wpf;
    const unsigned* pB = isv? g_Wfvf: g_Wfpf;
    float* outA = (isv? g_v : g_p)  + (size_t)rb*128;
    float* outB = (isv? g_V1: g_P1) + (size_t)rb*128;
    int t=threadIdx.x, w=t>>5, lane=t&31, gid=lane>>2, t4=lane&3;
    uint32_t Wsa = s2u(W_s);
    uint32_t mb  = Wsa + 13568*4;
    if(t==0) MBAR_INIT(mb, 1);
    if(t<128) bias_s[t] = isv? bv[t]: bp[t];
    else      bias_s[t] = g_biasF[isv*128 + (t-128)];
    int sub=((t&31)>>4)*2 + ((t&15)>>3), gid4=(t&7)*4, bgrp=(t>>5)*1024;
    int rowgrp=w&3, pk=w>>2;
    float acc[2][16][4];
#pragma unroll
    for(int mi=0;mi<2;mi++)
#pragma unroll
        for(int j=0;j<16;j++)
#pragma unroll
            for(int e=0;e<4;e++) acc[mi][j][e]=0.f;
    __syncthreads();
    for(int s=0;s<4;s++){
        if(s) __syncthreads();
        if(t==0){
            MBAR_EXPECT(mb, 36864);
            bulkcp(Wsa,        pA + s*4608, 18432, mb);
            bulkcp(Wsa+18432,  pB + s*4608, 18432, mb);
        }
        if(t<128){
            const float4* row = (const float4*)(in + (size_t)t*128 + s*32);
#pragma unroll
            for(int g=0;g<8;g++){
                float4 a=row[g];
                uint4 o={f2tf(a.x),f2tf(a.y),f2tf(a.z),f2tf(a.w)};
                *(uint4*)&A_f[bgrp + (g*4+sub)*32 + gid4] = o;
            }
        }
        mbwait(mb, s&1);
        __syncthreads();
        mma_slab(acc, A_f + rowgrp*1024, W_s + pk*4608, lane);
    }
    float* outX = pk? outB: outA;
#pragma unroll
    for(int mi=0;mi<2;mi++){
        int r0 = rowgrp*32 + mi*16 + gid;
#pragma unroll
        for(int j=0;j<16;j++){
            int c=j*8+2*t4;
            float b0=bias_s[pk*128+c], b1=bias_s[pk*128+c+1];
            *(float2*)&outX[(size_t)r0*128+c]     = make_float2(acc[mi][j][0]+b0, acc[mi][j][1]+b1);
            *(float2*)&outX[(size_t)(r0+8)*128+c] = make_float2(acc[mi][j][2]+b0, acc[mi][j][3]+b1);
        }
    }
}

// A-fragment build (bases include +2*t4)
DI void buildA(unsigned ah[4][4], const float* pw, const float* v0, const float* v1, int s){
    const int kb0 = (s&1)*64;
    const float* pwk = pw + kb0;
    const float* v0k = v0 + kb0;
    const float* v1k = v1 + kb0;
#pragma unroll
    for(int ks=0;ks<4;ks++){
        int ko = ks*16;
        float2 pl = *(const float2*)&pwk[ko];
        float2 ph = *(const float2*)&pwk[ko+8];
        float2 a0=*(const float2*)&v0k[ko],   c0=*(const float2*)&v1k[ko];
        float2 a1=*(const float2*)&v0k[ko+8], c1=*(const float2*)&v1k[ko+8];
        if(s<2){
            ah[ks][0]=pk2(pl.x*a0.x, pl.y*a0.y);
            ah[ks][1]=pk2(pl.x*c0.x, pl.y*c0.y);
            ah[ks][2]=pk2(ph.x*a1.x, ph.y*a1.y);
            ah[ks][3]=pk2(ph.x*c1.x, ph.y*c1.y);
        }else{
            ah[ks][0]=pk2(fabsf(pl.x-a0.x), fabsf(pl.y-a0.y));
            ah[ks][1]=pk2(fabsf(pl.x-c0.x), fabsf(pl.y-c0.y));
            ah[ks][2]=pk2(fabsf(ph.x-a1.x), fabsf(ph.y-a1.y));
            ah[ks][3]=pk2(fabsf(ph.x-c1.x), fabsf(ph.y-c1.y));
        }
    }
}

DI void mmaW(float (*acc)[4], const unsigned ah[4][4], const unsigned* Wb, int lane){
#pragma unroll
    for(int ks=0;ks<4;ks++){
        const uint4* bb = (const uint4*)(Wb + (ks*32+lane)*36);
#pragma unroll
        for(int jj=0;jj<8;jj++){
            uint4 b = bb[jj];
            mma16(acc[2*jj],  ah[ks][0],ah[ks][1],ah[ks][2],ah[ks][3],b.x,b.y);
            mma16(acc[2*jj+1],ah[ks][0],ah[ks][1],ah[ks][2],ah[ks][3],b.z,b.w);
        }
    }
}

DI void mmaH(float (*acc)[4], const unsigned h2[16][2], int s2, const unsigned* Wb, int lane){
#pragma unroll
    for(int ks=0;ks<4;ks++){
        int kg = s2*4+ks;
        const uint4* bb = (const uint4*)(Wb + (ks*32+lane)*36);
#pragma unroll
        for(int jj=0;jj<8;jj++){
            uint4 b = bb[jj];
            mma16(acc[2*jj],  h2[2*kg][0],h2[2*kg][1],h2[2*kg+1][0],h2[2*kg+1][1],b.x,b.y);
            mma16(acc[2*jj+1],h2[2*kg][0],h2[2*kg][1],h2[2*kg+1][0],h2[2*kg+1][1],b.z,b.w);
        }
    }
}

// ---------------------------------------------------------------------------
// pair_main v4 — PERSISTENT. 148 CTAs x 512 thr (16 warps, 1 CTA/SM).
// super-block sb = (bt<<2)|q : 256 pairs (n = q*8 + 0..7, m = 0..31).
// warp w owns rows w*16..w*16+15: n_local = w>>1, m = (w&1)*16 + 0..15.
// All 6 W slabs resident in smem; tiles double-buffered, prefetch distance 1.
// smem u32: W 6x4608 [0,27648) | TB0@27648 TB1@38528 (each: v 4352, V1 4352,
//   p 1088, P1 1088) | b1@49408 b2@49536 | mbars@49664 (mW, mt0, mt1)
// total 198688 B.
// ---------------------------------------------------------------------------
__global__ __launch_bounds__(512,1) void pair_main_kernel(
    const float* __restrict__ b1v, const float* __restrict__ b2v,
    float* __restrict__ out){
    extern __shared__ float sm[];
    unsigned* Wbuf = (unsigned*)sm;
    float* b1_s = sm + 49408;
    float* b2_s = sm + 49536;
    const int t=threadIdx.x, w=t>>5, lane=t&31;
    const int gid=lane>>2, t4=lane&3;
    const int n_local = w>>1, mbase = (w&1)*16;
    uint32_t Wba = s2u(Wbuf);
    uint32_t mW  = Wba + 49664*4;
    uint32_t mt0 = mW + 8, mt1 = mW + 16;

    if(t==0){ MBAR_INIT(mW,1); MBAR_INIT(mt0,80); MBAR_INIT(mt1,80); }
    __syncthreads();
    if(t==0){
        MBAR_EXPECT(mW, 6*18432 + 1024);
#pragma unroll
        for(int s=0;s<4;s++) bulkcp(Wba + s*18432, g_W1h + s*4608, 18432, mW);
        bulkcp(Wba + 4*18432, g_W2h,        18432, mW);
        bulkcp(Wba + 5*18432, g_W2h + 4608, 18432, mW);
        bulkcp(s2u(b1_s), b1v, 512, mW);
        bulkcp(s2u(b2_s), b2v, 512, mW);
    }

    // tile prefetch helper: 80 threads each copy one 512B row into buffer tb
    // t<32: v row t | t<64: V1 row | t<72: p row | t<80: P1 row
    auto prefetch = [&](int sb, uint32_t tb, uint32_t mt){
        if(t < 80){
            int bt = sb>>2, q = sb&3;
            uint32_t dst; const float* src;
            if(t < 32){       dst = tb + (uint32_t)t*544;        src = g_v  + (size_t)bt*4096 + t*128; }
            else if(t < 64){  dst = tb + 4352*4 + (t-32)*544;    src = g_V1 + (size_t)bt*4096 + (t-32)*128; }
            else if(t < 72){  dst = tb + 8704*4 + (t-64)*544;    src = g_p  + (size_t)(bt*32 + q*8 + (t-64))*128; }
            else           {  dst = tb + 9792*4 + (t-72)*544;    src = g_P1 + (size_t)(bt*32 + q*8 + (t-72))*128; }
            MBAR_EXPECT(mt, 512);
            bulkcp(dst, src, 512, mt);
        }
    };

    const uint32_t TB[2] = { Wba + 27648*4, Wba + 38528*4 };
    const uint32_t MT[2] = { mt0, mt1 };
    // prefetch first super-block into buf0
    prefetch(blockIdx.x, TB[0], MT[0]);

    mbwait(mW, 0);   // W + biases resident (all threads)

    int ph[2] = {0, 0};
    int it = 0;
    for(int sb = blockIdx.x; sb < 1024; sb += 148, it++){
        int buf = it & 1;
        __syncthreads();   // all warps done reading buf^1 (previous iteration)
        if(sb + 148 < 1024) prefetch(sb + 148, TB[buf^1], MT[buf^1]);
        mbwait(MT[buf], ph[buf]); ph[buf] ^= 1;

        const float* v_s  = (const float*)(size_t)0 + 0; // placeholder (unused)
        const float* tbv  = sm + (buf? 38528: 27648);
        const float* tbV1 = tbv + 4352;
        const float* tbp  = tbv + 8704;
        const float* tbP1 = tbv + 9792;

        const float* pw = tbp + n_local*136 + 2*t4;
        const float* v0 = tbv + (mbase+gid)*136 + 2*t4;
        const float* v1 = v0 + 8*136;

        float acc[16][4];
#pragma unroll
        for(int j=0;j<16;j++)
#pragma unroll
            for(int e=0;e<4;e++) acc[j][e]=0.f;

        unsigned ah[4][4];
        buildA(ah, pw, v0, v1, 0); mmaW(acc, ah, Wbuf,        lane);
        buildA(ah, pw, v0, v1, 1); mmaW(acc, ah, Wbuf+4608,   lane);
        buildA(ah, pw, v0, v1, 2); mmaW(acc, ah, Wbuf+2*4608, lane);
        buildA(ah, pw, v0, v1, 3); mmaW(acc, ah, Wbuf+3*4608, lane);

        // epilogue 1: silu(D + P1 + V1 + b1) -> half2 regs
        unsigned h2[16][2];
#pragma unroll
        for(int j=0;j<16;j++){
            int c0=j*8+2*t4;
            float2 P  =*(const float2*)&tbP1[n_local*136+c0];
            float2 Bb =*(const float2*)&b1_s[c0];
            float2 V0 =*(const float2*)&tbV1[(mbase+gid)*136+c0];
            float2 V1r=*(const float2*)&tbV1[(mbase+gid+8)*136+c0];
            float x0=acc[j][0]+P.x+V0.x+Bb.x;
            float x1=acc[j][1]+P.y+V0.y+Bb.y;
            float x2=acc[j][2]+P.x+V1r.x+Bb.x;
            float x3=acc[j][3]+P.y+V1r.y+Bb.y;
            x0=x0/(1.f+__expf(-x0)); x1=x1/(1.f+__expf(-x1));
            x2=x2/(1.f+__expf(-x2)); x3=x3/(1.f+__expf(-x3));
            h2[j][0]=pk2(x0,x1);
            h2[j][1]=pk2(x2,x3);
            acc[j][0]=0.f; acc[j][1]=0.f; acc[j][2]=0.f; acc[j][3]=0.f;
        }

        // GEMM2: resident W2 slabs (slots 4,5)
        mmaH(acc, h2, 0, Wbuf+4*4608, lane);
        mmaH(acc, h2, 1, Wbuf+5*4608, lane);

        // epilogue 2: + b2, direct stores
        float* o0 = out + ((size_t)sb*256 + w*16 + gid)*128;
        float* o1 = o0 + 8*128;
#pragma unroll
        for(int j=0;j<16;j++){
            int c=j*8+2*t4;
            *(float2*)&o0[c] = make_float2(acc[j][0]+b2_s[c], acc[j][1]+b2_s[c+1]);
            *(float2*)&o1[c] = make_float2(acc[j][2]+b2_s[c], acc[j][3]+b2_s[c+1]);
        }
        (void)v_s;
    }
}

extern "C" void kernel_launch(void* const* d_in, const int* in_sizes, int n_in,
                              void* d_out, int out_size){
    const float* price =(const float*)d_in[0];
    const float* liquid=(const float*)d_in[1];
    const float* W_p=(const float*)d_in[2];
    const float* b_p=(const float*)d_in[3];
    const float* W_v=(const float*)d_in[4];
    const float* b_v=(const float*)d_in[5];
    const float* W1 =(const float*)d_in[6];
    const float* b1 =(const float*)d_in[7];
    const float* W2 =(const float*)d_in[8];
    const float* b2 =(const float*)d_in[9];
    float* out=(float*)d_out;
    cudaFuncSetAttribute(pv_kernel, cudaFuncAttributeMaxDynamicSharedMemorySize, 55296);
    cudaFuncSetAttribute(pair_main_kernel, cudaFuncAttributeMaxDynamicSharedMemorySize, 198688);
    prep_kernel<<<16, 256>>>(W_p, b_p, W_v, b_v, W1);
    pack_kernel<<<16, 128>>>(W_p, W_v);
    pack16_kernel<<<6, 128>>>(W1, W2);
    pv_kernel<<<128, 256, 54280>>>(price, liquid, b_p, b_v);
    pair_main_kernel<<<148, 512, 198688>>>(b1, b2, out);
}

// round 14
// speedup vs baseline: 1.4291x; 1.4291x over previous
#include <cuda_runtime.h>
#include <cstdint>
#define DI __device__ __forceinline__

__device__ float g_p [8192*128];
__device__ float g_v [8192*128];
__device__ float g_P1[8192*128];
__device__ float g_V1[8192*128];
__device__ float g_Wfp[128*128];
__device__ float g_Wfv[128*128];
__device__ float g_biasF[2*128];
// tf32 fragment packs for pv prologue (k32 slabs, stride 36)
__device__ __align__(16) unsigned g_Wpf [4*4608];
__device__ __align__(16) unsigned g_Wfpf[4*4608];
__device__ __align__(16) unsigned g_Wvf [4*4608];
__device__ __align__(16) unsigned g_Wfvf[4*4608];
// fp16 fragment packs for main kernel (k64 slabs, stride 36)
__device__ __align__(16) unsigned g_W1h[4*4608];   // W1c|W1d rows 256..511
__device__ __align__(16) unsigned g_W2h[2*4608];

DI unsigned f2tf(float x){ unsigned r; asm("cvt.rna.tf32.f32 %0, %1;":"=r"(r):"f"(x)); return r; }
DI unsigned pk2(float lo, float hi){
    unsigned r;
    asm("cvt.rn.f16x2.f32 %0, %1, %2;" : "=r"(r) : "f"(hi), "f"(lo));
    return r;
}
DI float frcp(float x){ float r; asm("rcp.approx.f32 %0, %1;":"=f"(r):"f"(x)); return r; }
DI void mma8(float* c, unsigned a0,unsigned a1,unsigned a2,unsigned a3,unsigned b0,unsigned b1){
    asm volatile("mma.sync.aligned.m16n8k8.row.col.f32.tf32.tf32.f32 "
        "{%0,%1,%2,%3},{%4,%5,%6,%7},{%8,%9},{%0,%1,%2,%3};\n"
        :"+f"(c[0]),"+f"(c[1]),"+f"(c[2]),"+f"(c[3])
        :"r"(a0),"r"(a1),"r"(a2),"r"(a3),"r"(b0),"r"(b1)); }
DI void mma16(float* c, unsigned a0,unsigned a1,unsigned a2,unsigned a3,unsigned b0,unsigned b1){
    asm volatile("mma.sync.aligned.m16n8k16.row.col.f32.f16.f16.f32 "
        "{%0,%1,%2,%3},{%4,%5,%6,%7},{%8,%9},{%0,%1,%2,%3};\n"
        :"+f"(c[0]),"+f"(c[1]),"+f"(c[2]),"+f"(c[3])
        :"r"(a0),"r"(a1),"r"(a2),"r"(a3),"r"(b0),"r"(b1)); }
DI uint32_t s2u(const void* p){ uint32_t a; asm("{ .reg .u64 t; cvta.to.shared.u64 t, %1; cvt.u32.u64 %0, t; }":"=r"(a):"l"(p)); return a; }

// ---- bulk async copy (UBLKCP) + mbarrier ----
DI void bulkcp(uint32_t dst, const void* src, uint32_t bytes, uint32_t mbar){
    asm volatile("cp.async.bulk.shared::cta.global.mbarrier::complete_tx::bytes [%0], [%1], %2, [%3];"
                 :: "r"(dst), "l"(src), "r"(bytes), "r"(mbar) : "memory");
}
#define MBAR_INIT(a,n)   asm volatile("mbarrier.init.shared.b64 [%0], %1;"::"r"(a),"r"(n):"memory")
#define MBAR_EXPECT(a,b) asm volatile("mbarrier.arrive.expect_tx.shared.b64 _, [%0], %1;"::"r"(a),"r"(b):"memory")
DI void mbwait(uint32_t mb, uint32_t par){
    uint32_t done;
    asm volatile("{\n\t.reg .pred p;\n\tmbarrier.try_wait.parity.acquire.cta.shared::cta.b64 p, [%1], %2;\n\tselp.b32 %0,1,0,p;\n\t}"
        :"=r"(done):"r"(mb),"r"(par):"memory");
    if(!done) asm volatile("{\n\t.reg .pred P1;\n\tWL_%=:\n\t"
        "mbarrier.try_wait.parity.acquire.cta.shared::cta.b64 P1, [%0], %1, 0x989680;\n\t"
        "@P1 bra.uni WD_%=;\n\tbra.uni WL_%=;\n\tWD_%=:\n\t}"::"r"(mb),"r"(par):"memory");
}

// tf32 slab mma for pv kernel (unchanged, proven)
DI void mma_slab(float (*acc)[16][4], const unsigned* Ab, const unsigned* Wb, int lane){
#pragma unroll
    for(int ks=0; ks<4; ks++){
        unsigned a[2][4];
#pragma unroll
        for(int mi=0; mi<2; mi++){
            int c0 = ks*8 + mi*2;
            a[mi][0]=Ab[(c0+0)*32+lane]; a[mi][1]=Ab[(c0+1)*32+lane];
            a[mi][2]=Ab[(c0+4)*32+lane]; a[mi][3]=Ab[(c0+5)*32+lane];
        }
        const uint4* bb = (const uint4*)(Wb + (ks*32+lane)*36);
#pragma unroll
        for(int jj=0; jj<8; jj++){
            uint4 b = bb[jj];
            mma8(acc[0][2*jj],  a[0][0],a[0][1],a[0][2],a[0][3],b.x,b.y);
            mma8(acc[1][2*jj],  a[1][0],a[1][1],a[1][2],a[1][3],b.x,b.y);
            mma8(acc[0][2*jj+1],a[0][0],a[0][1],a[0][2],a[0][3],b.z,b.w);
            mma8(acc[1][2*jj+1],a[1][0],a[1][1],a[1][2],a[1][3],b.z,b.w);
        }
    }
}

__global__ __launch_bounds__(256) void prep_kernel(
    const float* __restrict__ Wp, const float* __restrict__ bp,
    const float* __restrict__ Wv, const float* __restrict__ bv,
    const float* __restrict__ W1){
    __shared__ float Wc_s[32*128];
    __shared__ float Wr_s[16*128];
    int cb = blockIdx.x, isv = cb>=8, rb = (cb&7)*16;
    const float* Wx  = isv? Wv: Wp;
    const float* W1x = W1 + (isv? 128*128: 0);
    float* outW = isv? g_Wfv: g_Wfp;
    int t = threadIdx.x;
    for(int i=t; i<16*128; i+=256) Wr_s[i] = Wx[(rb+(i>>7))*128 + (i&127)];
    float acc[8];
#pragma unroll
    for(int ii=0; ii<8; ii++) acc[ii]=0.f;
    int j = t&127, ih = (t>>7)*8;
    for(int kc=0; kc<4; kc++){
        __syncthreads();
        for(int i=t; i<32*128; i+=256) Wc_s[i] = W1x[(kc*32+(i>>7))*128 + (i&127)];
        __syncthreads();
        for(int k=0; k<32; k++){
            float b = Wc_s[k*128+j];
#pragma unroll
            for(int ii=0; ii<8; ii++) acc[ii] += Wr_s[(ih+ii)*128 + kc*32+k]*b;
        }
    }
#pragma unroll
    for(int ii=0; ii<8; ii++) outW[(rb+ih+ii)*128 + j] = acc[ii];
    if((cb&7)==0 && t<128){
        const float* bx = isv? bv: bp;
        float s=0.f;
        for(int k=0;k<128;k++) s += bx[k]*W1x[k*128+t];
        g_biasF[isv*128+t] = s;
    }
}

__global__ __launch_bounds__(128) void pack_kernel(
    const float* __restrict__ Wp, const float* __restrict__ Wv){
    int sid = blockIdx.x;
    const float* src; unsigned* dst;
    if      (sid<4) { src = Wp + sid*32*128;          dst = g_Wpf  + sid*4608; }
    else if (sid<8) { src = g_Wfp + (sid-4)*32*128;   dst = g_Wfpf + (sid-4)*4608; }
    else if (sid<12){ src = Wv + (sid-8)*32*128;      dst = g_Wvf  + (sid-8)*4608; }
    else            { src = g_Wfv + (sid-12)*32*128;  dst = g_Wfvf + (sid-12)*4608; }
    int t=threadIdx.x, lane=t&31, ks=t>>5, gid=lane>>2, t4=lane&3;
#pragma unroll
    for(int j=0;j<16;j++)
#pragma unroll
        for(int r=0;r<2;r++)
            dst[(ks*32+lane)*36 + 2*j + r] = f2tf(src[(ks*8+t4+r*4)*128 + j*8 + gid]);
}

// fp16 fragment pack for main-kernel weights. grid 6 x 128.
__global__ __launch_bounds__(128) void pack16_kernel(
    const float* __restrict__ W1, const float* __restrict__ W2){
    int sid = blockIdx.x;
    const float* src; unsigned* dst;
    if(sid<4){ src = W1 + (256 + sid*64)*128; dst = g_W1h + sid*4608; }
    else     { src = W2 + (sid-4)*64*128;     dst = g_W2h + (sid-4)*4608; }
    int t=threadIdx.x, lane=t&31, ks=t>>5, gid=lane>>2, t4=lane&3;
#pragma unroll
    for(int j=0;j<16;j++)
#pragma unroll
        for(int r=0;r<2;r++){
            int k0 = ks*16 + 2*t4 + 8*r;
            dst[(ks*32+lane)*36 + 2*j + r] =
                pk2(src[k0*128 + 8*j + gid], src[(k0+1)*128 + 8*j + gid]);
        }
}

// pv: bulk-copy version (R12, passing)
__global__ __launch_bounds__(256) void pv_kernel(
    const float* __restrict__ price, const float* __restrict__ liquid,
    const float* __restrict__ bp, const float* __restrict__ bv){
    extern __shared__ float smpv[];
    unsigned* W_s = (unsigned*)smpv;
    unsigned* A_f = (unsigned*)smpv + 9216;
    float* bias_s = smpv + 13312;
    int cb=blockIdx.x, isv=cb>=64, rb=(cb&63)*128;
    const float* in = (isv? liquid: price) + (size_t)rb*128;
    const unsigned* pA = isv? g_Wvf : g_Wpf;
    const unsigned* pB = isv? g_Wfvf: g_Wfpf;
    float* outA = (isv? g_v : g_p)  + (size_t)rb*128;
    float* outB = (isv? g_V1: g_P1) + (size_t)rb*128;
    int t=threadIdx.x, w=t>>5, lane=t&31, gid=lane>>2, t4=lane&3;
    uint32_t Wsa = s2u(W_s);
    uint32_t mb  = Wsa + 13568*4;
    if(t==0) MBAR_INIT(mb, 1);
    if(t<128) bias_s[t] = isv? bv[t]: bp[t];
    else      bias_s[t] = g_biasF[isv*128 + (t-128)];
    int sub=((t&31)>>4)*2 + ((t&15)>>3), gid4=(t&7)*4, bgrp=(t>>5)*1024;
    int rowgrp=w&3, pk=w>>2;
    float acc[2][16][4];
#pragma unroll
    for(int mi=0;mi<2;mi++)
#pragma unroll
        for(int j=0;j<16;j++)
#pragma unroll
            for(int e=0;e<4;e++) acc[mi][j][e]=0.f;
    __syncthreads();
    for(int s=0;s<4;s++){
        if(s) __syncthreads();
        if(t==0){
            MBAR_EXPECT(mb, 36864);
            bulkcp(Wsa,        pA + s*4608, 18432, mb);
            bulkcp(Wsa+18432,  pB + s*4608, 18432, mb);
        }
        if(t<128){
            const float4* row = (const float4*)(in + (size_t)t*128 + s*32);
#pragma unroll
            for(int g=0;g<8;g++){
                float4 a=row[g];
                uint4 o={f2tf(a.x),f2tf(a.y),f2tf(a.z),f2tf(a.w)};
                *(uint4*)&A_f[bgrp + (g*4+sub)*32 + gid4] = o;
            }
        }
        mbwait(mb, s&1);
        __syncthreads();
        mma_slab(acc, A_f + rowgrp*1024, W_s + pk*4608, lane);
    }
    float* outX = pk? outB: outA;
#pragma unroll
    for(int mi=0;mi<2;mi++){
        int r0 = rowgrp*32 + mi*16 + gid;
#pragma unroll
        for(int j=0;j<16;j++){
            int c=j*8+2*t4;
            float b0=bias_s[pk*128+c], b1=bias_s[pk*128+c+1];
            *(float2*)&outX[(size_t)r0*128+c]     = make_float2(acc[mi][j][0]+b0, acc[mi][j][1]+b1);
            *(float2*)&outX[(size_t)(r0+8)*128+c] = make_float2(acc[mi][j][2]+b0, acc[mi][j][3]+b1);
        }
    }
}

// A-fragment build (bases include +2*t4)
DI void buildA(unsigned ah[4][4], const float* pw, const float* v0, const float* v1, int s){
    const int kb0 = (s&1)*64;
    const float* pwk = pw + kb0;
    const float* v0k = v0 + kb0;
    const float* v1k = v1 + kb0;
#pragma unroll
    for(int ks=0;ks<4;ks++){
        int ko = ks*16;
        float2 pl = *(const float2*)&pwk[ko];
        float2 ph = *(const float2*)&pwk[ko+8];
        float2 a0=*(const float2*)&v0k[ko],   c0=*(const float2*)&v1k[ko];
        float2 a1=*(const float2*)&v0k[ko+8], c1=*(const float2*)&v1k[ko+8];
        if(s<2){
            ah[ks][0]=pk2(pl.x*a0.x, pl.y*a0.y);
            ah[ks][1]=pk2(pl.x*c0.x, pl.y*c0.y);
            ah[ks][2]=pk2(ph.x*a1.x, ph.y*a1.y);
            ah[ks][3]=pk2(ph.x*c1.x, ph.y*c1.y);
        }else{
            ah[ks][0]=pk2(fabsf(pl.x-a0.x), fabsf(pl.y-a0.y));
            ah[ks][1]=pk2(fabsf(pl.x-c0.x), fabsf(pl.y-c0.y));
            ah[ks][2]=pk2(fabsf(ph.x-a1.x), fabsf(ph.y-a1.y));
            ah[ks][3]=pk2(fabsf(ph.x-c1.x), fabsf(ph.y-c1.y));
        }
    }
}

DI void mmaW(float (*acc)[4], const unsigned ah[4][4], const unsigned* Wb, int lane){
#pragma unroll
    for(int ks=0;ks<4;ks++){
        const uint4* bb = (const uint4*)(Wb + (ks*32+lane)*36);
#pragma unroll
        for(int jj=0;jj<8;jj++){
            uint4 b = bb[jj];
            mma16(acc[2*jj],  ah[ks][0],ah[ks][1],ah[ks][2],ah[ks][3],b.x,b.y);
            mma16(acc[2*jj+1],ah[ks][0],ah[ks][1],ah[ks][2],ah[ks][3],b.z,b.w);
        }
    }
}

DI void mmaH(float (*acc)[4], const unsigned h2[16][2], int s2, const unsigned* Wb, int lane){
#pragma unroll
    for(int ks=0;ks<4;ks++){
        int kg = s2*4+ks;
        const uint4* bb = (const uint4*)(Wb + (ks*32+lane)*36);
#pragma unroll
        for(int jj=0;jj<8;jj++){
            uint4 b = bb[jj];
            mma16(acc[2*jj],  h2[2*kg][0],h2[2*kg][1],h2[2*kg+1][0],h2[2*kg+1][1],b.x,b.y);
            mma16(acc[2*jj+1],h2[2*kg][0],h2[2*kg][1],h2[2*kg+1][0],h2[2*kg+1][1],b.z,b.w);
        }
    }
}

// ---------------------------------------------------------------------------
// main (R12 structure): 2048 CTAs x 256 thr / 8 warps, bulk-copy loads,
// 4-slot W ring + tile mbar. Epilogue1 uses 4-way batched rcp (1 MUFU / 4 elems).
// smem u32: Wbuf 4x4608 [0,18432) | b1@18432 b2@18560 | v@18688 (32x136) |
//   V1@23040 | p@27392 (4x136) | P1@27936..28480 | mbars@28480
// total 113960 B -> 2 CTAs/SM.
// ---------------------------------------------------------------------------
__global__ __launch_bounds__(256,2) void pair_main_kernel(
    const float* __restrict__ b1v, const float* __restrict__ b2v,
    float* __restrict__ out){
    extern __shared__ float sm[];
    unsigned* Wbuf = (unsigned*)sm;
    float* b1_s = sm + 18432;
    float* b2_s = sm + 18560;
    float* v_s  = sm + 18688;
    float* V1_s = sm + 23040;
    float* p_s  = sm + 27392;
    float* P1_s = sm + 27936;
    const int bt=blockIdx.x>>3, pb=blockIdx.x&7;
    const int t=threadIdx.x, w=t>>5, lane=t&31;
    const int gid=lane>>2, t4=lane&3;
    const int n = w>>1, mbase = (w&1)*16;
    uint32_t Wba = s2u(Wbuf);
    uint32_t m0 = Wba + 28480*4;
    uint32_t m1 = m0+8, m2 = m0+16, m3 = m0+24, mt = m0+32;

    if(t==0){
        MBAR_INIT(m0,1); MBAR_INIT(m1,1); MBAR_INIT(m2,1);
        MBAR_INIT(m3,1); MBAR_INIT(mt,1);
    }
    __syncthreads();   // mbar init visible
    if(t==0){
        MBAR_EXPECT(m0,18432); bulkcp(Wba,         g_W1h,        18432, m0);
        MBAR_EXPECT(m1,18432); bulkcp(Wba+18432,   g_W1h+4608,   18432, m1);
        MBAR_EXPECT(m2,18432); bulkcp(Wba+2*18432, g_W1h+2*4608, 18432, m2);
        MBAR_EXPECT(m3,18432); bulkcp(Wba+3*18432, g_W1h+3*4608, 18432, m3);
        MBAR_EXPECT(mt, 32*512*2 + 4*512*2 + 1024);
        uint32_t vA = s2u(v_s), vB = s2u(V1_s), pA = s2u(p_s), pB = s2u(P1_s);
        const float* vg  = g_v  + (size_t)bt*4096;
        const float* V1g = g_V1 + (size_t)bt*4096;
        for(int m=0;m<32;m++){
            bulkcp(vA + m*544, vg  + m*128, 512, mt);
            bulkcp(vB + m*544, V1g + m*128, 512, mt);
        }
        const float* pg  = g_p  + (size_t)(bt*32+pb*4)*128;
        const float* P1g = g_P1 + (size_t)(bt*32+pb*4)*128;
        for(int nn=0;nn<4;nn++){
            bulkcp(pA + nn*544, pg  + nn*128, 512, mt);
            bulkcp(pB + nn*544, P1g + nn*128, 512, mt);
        }
        bulkcp(s2u(b1_s), b1v, 512, mt);
        bulkcp(s2u(b2_s), b2v, 512, mt);
    }

    float acc[16][4];
#pragma unroll
    for(int j=0;j<16;j++)
#pragma unroll
        for(int e=0;e<4;e++) acc[j][e]=0.f;

    mbwait(mt, 0);   // tiles ready
    const float* pw = p_s + n*136 + 2*t4;
    const float* v0 = v_s + (mbase+gid)*136 + 2*t4;
    const float* v1 = v0 + 8*136;

    unsigned ah[4][4];
    buildA(ah, pw, v0, v1, 0);
    mbwait(m0, 0);
    mmaW(acc, ah, Wbuf, lane);
    buildA(ah, pw, v0, v1, 1);
    mbwait(m1, 0);
    mmaW(acc, ah, Wbuf+4608, lane);
    __syncthreads();
    if(t==0){
        MBAR_EXPECT(m0,18432); bulkcp(Wba,       g_W2h,      18432, m0);
        MBAR_EXPECT(m1,18432); bulkcp(Wba+18432, g_W2h+4608, 18432, m1);
    }
    buildA(ah, pw, v0, v1, 2);
    mbwait(m2, 0);
    mmaW(acc, ah, Wbuf+2*4608, lane);
    buildA(ah, pw, v0, v1, 3);
    mbwait(m3, 0);
    mmaW(acc, ah, Wbuf+3*4608, lane);

    // ------- epilogue 1: silu via 4-way batched reciprocal ------------------
    unsigned h2[16][2];
#pragma unroll
    for(int j=0;j<16;j++){
        int c0=j*8+2*t4;
        float2 P  =*(const float2*)&P1_s[n*136+c0];
        float2 Bb =*(const float2*)&b1_s[c0];
        float2 V0 =*(const float2*)&V1_s[(mbase+gid)*136+c0];
        float2 V1r=*(const float2*)&V1_s[(mbase+gid+8)*136+c0];
        float x0=acc[j][0]+P.x+V0.x+Bb.x;
        float x1=acc[j][1]+P.y+V0.y+Bb.y;
        float x2=acc[j][2]+P.x+V1r.x+Bb.x;
        float x3=acc[j][3]+P.y+V1r.y+Bb.y;
        float u0=1.f+__expf(-x0), u1=1.f+__expf(-x1);
        float u2=1.f+__expf(-x2), u3=1.f+__expf(-x3);
        float p01=u0*u1, p23=u2*u3;
        float r = frcp(p01*p23);
        float r01 = r*p23, r23 = r*p01;   // 1/(u0*u1), 1/(u2*u3)
        x0 = x0*(r01*u1); x1 = x1*(r01*u0);
        x2 = x2*(r23*u3); x3 = x3*(r23*u2);
        h2[j][0]=pk2(x0,x1);
        h2[j][1]=pk2(x2,x3);
        acc[j][0]=0.f; acc[j][1]=0.f; acc[j][2]=0.f; acc[j][3]=0.f;
    }

    // ---- GEMM2: W2 slabs 0,1 (slots 0,1 phase 1), A from h2 regs ----
    mbwait(m0, 1);
    mmaH(acc, h2, 0, Wbuf, lane);
    mbwait(m1, 1);
    mmaH(acc, h2, 1, Wbuf+4608, lane);

    // ------------- epilogue 2: + b2, direct stores ----------------
    const size_t ob = (size_t)blockIdx.x*16384;
    float* o0 = out + ob + (size_t)(w*16+gid)*128;
    float* o1 = o0 + 1024;
#pragma unroll
    for(int j=0;j<16;j++){
        int c=j*8+2*t4;
        *(float2*)&o0[c] = make_float2(acc[j][0]+b2_s[c], acc[j][1]+b2_s[c+1]);
        *(float2*)&o1[c] = make_float2(acc[j][2]+b2_s[c], acc[j][3]+b2_s[c+1]);
    }
}

extern "C" void kernel_launch(void* const* d_in, const int* in_sizes, int n_in,
                              void* d_out, int out_size){
    const float* price =(const float*)d_in[0];
    const float* liquid=(const float*)d_in[1];
    const float* W_p=(const float*)d_in[2];
    const float* b_p=(const float*)d_in[3];
    const float* W_v=(const float*)d_in[4];
    const float* b_v=(const float*)d_in[5];
    const float* W1 =(const float*)d_in[6];
    const float* b1 =(const float*)d_in[7];
    const float* W2 =(const float*)d_in[8];
    const float* b2 =(const float*)d_in[9];
    float* out=(float*)d_out;
    cudaFuncSetAttribute(pv_kernel, cudaFuncAttributeMaxDynamicSharedMemorySize, 55296);
    cudaFuncSetAttribute(pair_main_kernel, cudaFuncAttributeMaxDynamicSharedMemorySize, 114688);
    prep_kernel<<<16, 256>>>(W_p, b_p, W_v, b_v, W1);
    pack_kernel<<<16, 128>>>(W_p, W_v);
    pack16_kernel<<<6, 128>>>(W1, W2);
    pv_kernel<<<128, 256, 54280>>>(price, liquid, b_p, b_v);
    pair_main_kernel<<<2048, 256, 113960>>>(b1, b2, out);
}

// round 15
// speedup vs baseline: 1.5353x; 1.0743x over previous
#include <cuda_runtime.h>
#include <cstdint>
#define DI __device__ __forceinline__

__device__ float g_p [8192*128];
__device__ float g_v [8192*128];
__device__ float g_P1[8192*128];
__device__ float g_V1[8192*128];
__device__ float g_Wfp[128*128];
__device__ float g_Wfv[128*128];
__device__ float g_biasF[2*128];
// fp16 fragment packs (k64 slabs, stride 36)
__device__ __align__(16) unsigned g_W1h [4*4608];   // W1c|W1d rows 256..511
__device__ __align__(16) unsigned g_W2h [2*4608];
__device__ __align__(16) unsigned g_Wph [2*4608];
__device__ __align__(16) unsigned g_Wfph[2*4608];
__device__ __align__(16) unsigned g_Wvh [2*4608];
__device__ __align__(16) unsigned g_Wfvh[2*4608];

DI unsigned pk2(float lo, float hi){
    unsigned r;
    asm("cvt.rn.f16x2.f32 %0, %1, %2;" : "=r"(r) : "f"(hi), "f"(lo));
    return r;
}
DI float frcp(float x){ float r; asm("rcp.approx.f32 %0, %1;":"=f"(r):"f"(x)); return r; }
DI void mma16(float* c, unsigned a0,unsigned a1,unsigned a2,unsigned a3,unsigned b0,unsigned b1){
    asm volatile("mma.sync.aligned.m16n8k16.row.col.f32.f16.f16.f32 "
        "{%0,%1,%2,%3},{%4,%5,%6,%7},{%8,%9},{%0,%1,%2,%3};\n"
        :"+f"(c[0]),"+f"(c[1]),"+f"(c[2]),"+f"(c[3])
        :"r"(a0),"r"(a1),"r"(a2),"r"(a3),"r"(b0),"r"(b1)); }
DI uint32_t s2u(const void* p){ uint32_t a; asm("{ .reg .u64 t; cvta.to.shared.u64 t, %1; cvt.u32.u64 %0, t; }":"=r"(a):"l"(p)); return a; }

// ---- bulk async copy (UBLKCP) + mbarrier ----
DI void bulkcp(uint32_t dst, const void* src, uint32_t bytes, uint32_t mbar){
    asm volatile("cp.async.bulk.shared::cta.global.mbarrier::complete_tx::bytes [%0], [%1], %2, [%3];"
                 :: "r"(dst), "l"(src), "r"(bytes), "r"(mbar) : "memory");
}
#define MBAR_INIT(a,n)   asm volatile("mbarrier.init.shared.b64 [%0], %1;"::"r"(a),"r"(n):"memory")
#define MBAR_EXPECT(a,b) asm volatile("mbarrier.arrive.expect_tx.shared.b64 _, [%0], %1;"::"r"(a),"r"(b):"memory")
DI void mbwait(uint32_t mb, uint32_t par){
    uint32_t done;
    asm volatile("{\n\t.reg .pred p;\n\tmbarrier.try_wait.parity.acquire.cta.shared::cta.b64 p, [%1], %2;\n\tselp.b32 %0,1,0,p;\n\t}"
        :"=r"(done):"r"(mb),"r"(par):"memory");
    if(!done) asm volatile("{\n\t.reg .pred P1;\n\tWL_%=:\n\t"
        "mbarrier.try_wait.parity.acquire.cta.shared::cta.b64 P1, [%0], %1, 0x989680;\n\t"
        "@P1 bra.uni WD_%=;\n\tbra.uni WL_%=;\n\tWD_%=:\n\t}"::"r"(mb),"r"(par):"memory");
}

__global__ __launch_bounds__(256) void prep_kernel(
    const float* __restrict__ Wp, const float* __restrict__ bp,
    const float* __restrict__ Wv, const float* __restrict__ bv,
    const float* __restrict__ W1){
    __shared__ float Wc_s[32*128];
    __shared__ float Wr_s[16*128];
    int cb = blockIdx.x, isv = cb>=8, rb = (cb&7)*16;
    const float* Wx  = isv? Wv: Wp;
    const float* W1x = W1 + (isv? 128*128: 0);
    float* outW = isv? g_Wfv: g_Wfp;
    int t = threadIdx.x;
    for(int i=t; i<16*128; i+=256) Wr_s[i] = Wx[(rb+(i>>7))*128 + (i&127)];
    float acc[8];
#pragma unroll
    for(int ii=0; ii<8; ii++) acc[ii]=0.f;
    int j = t&127, ih = (t>>7)*8;
    for(int kc=0; kc<4; kc++){
        __syncthreads();
        for(int i=t; i<32*128; i+=256) Wc_s[i] = W1x[(kc*32+(i>>7))*128 + (i&127)];
        __syncthreads();
        for(int k=0; k<32; k++){
            float b = Wc_s[k*128+j];
#pragma unroll
            for(int ii=0; ii<8; ii++) acc[ii] += Wr_s[(ih+ii)*128 + kc*32+k]*b;
        }
    }
#pragma unroll
    for(int ii=0; ii<8; ii++) outW[(rb+ih+ii)*128 + j] = acc[ii];
    if((cb&7)==0 && t<128){
        const float* bx = isv? bv: bp;
        float s=0.f;
        for(int k=0;k<128;k++) s += bx[k]*W1x[k*128+t];
        g_biasF[isv*128+t] = s;
    }
}

// fp16 fragment pack, 14 k64 slabs. grid 14 x 128. (Runs after prep.)
__global__ __launch_bounds__(128) void pack16_kernel(
    const float* __restrict__ W1, const float* __restrict__ W2,
    const float* __restrict__ Wp, const float* __restrict__ Wv){
    int sid = blockIdx.x;
    const float* src; unsigned* dst;
    if      (sid<4) { src = W1 + (256 + sid*64)*128; dst = g_W1h  + sid*4608; }
    else if (sid<6) { src = W2 + (sid-4)*64*128;     dst = g_W2h  + (sid-4)*4608; }
    else if (sid<8) { src = Wp + (sid-6)*64*128;     dst = g_Wph  + (sid-6)*4608; }
    else if (sid<10){ src = g_Wfp + (sid-8)*64*128;  dst = g_Wfph + (sid-8)*4608; }
    else if (sid<12){ src = Wv + (sid-10)*64*128;    dst = g_Wvh  + (sid-10)*4608; }
    else            { src = g_Wfv + (sid-12)*64*128; dst = g_Wfvh + (sid-12)*4608; }
    int t=threadIdx.x, lane=t&31, ks=t>>5, gid=lane>>2, t4=lane&3;
#pragma unroll
    for(int j=0;j<16;j++)
#pragma unroll
        for(int r=0;r<2;r++){
            int k0 = ks*16 + 2*t4 + 8*r;
            dst[(ks*32+lane)*36 + 2*j + r] =
                pk2(src[k0*128 + 8*j + gid], src[(k0+1)*128 + 8*j + gid]);
        }
}

DI void mmaW(float (*acc)[4], const unsigned ah[4][4], const unsigned* Wb, int lane){
#pragma unroll
    for(int ks=0;ks<4;ks++){
        const uint4* bb = (const uint4*)(Wb + (ks*32+lane)*36);
#pragma unroll
        for(int jj=0;jj<8;jj++){
            uint4 b = bb[jj];
            mma16(acc[2*jj],  ah[ks][0],ah[ks][1],ah[ks][2],ah[ks][3],b.x,b.y);
            mma16(acc[2*jj+1],ah[ks][0],ah[ks][1],ah[ks][2],ah[ks][3],b.z,b.w);
        }
    }
}

// ---------------------------------------------------------------------------
// pv (fp16): 256 CTAs x 256 thr. CTA = 64 input rows; computes X@Wx (+b) and
// X@Wfx (+biasF). Warp: rowgrp=(w&3) 16 rows, pk=w>>2 selects weight pack.
// smem u32: Wres 4x4608 [0,18432) | in 64x136 f [18432,27136) |
//   bias 256 f [27136,27392) | mbar @27392.  109576 B -> 2 CTAs/SM.
// ---------------------------------------------------------------------------
__global__ __launch_bounds__(256,2) void pv_kernel(
    const float* __restrict__ price, const float* __restrict__ liquid,
    const float* __restrict__ bp, const float* __restrict__ bv){
    extern __shared__ float smpv[];
    unsigned* Wres = (unsigned*)smpv;
    float* in_s   = smpv + 18432;
    float* bias_s = smpv + 27136;
    int cb=blockIdx.x, isv=cb>=128, rb=(cb&127)*64;
    const float* in_g = (isv? liquid: price) + (size_t)rb*128;
    const unsigned* packA = isv? g_Wvh : g_Wph;
    const unsigned* packB = isv? g_Wfvh: g_Wfph;
    float* outA = (isv? g_v : g_p)  + (size_t)rb*128;
    float* outB = (isv? g_V1: g_P1) + (size_t)rb*128;
    int t=threadIdx.x, w=t>>5, lane=t&31, gid=lane>>2, t4=lane&3;
    int rowgrp=w&3, pk=w>>2, mbase=rowgrp*16;
    uint32_t sb = s2u(smpv);
    uint32_t mb = sb + 27392*4;

    if(t==0) MBAR_INIT(mb, 1);
    __syncthreads();
    if(t==0){
        MBAR_EXPECT(mb, 4*18432 + 64*512 + 1024);
        bulkcp(sb,          packA,        18432, mb);
        bulkcp(sb+18432,    packA+4608,   18432, mb);
        bulkcp(sb+2*18432,  packB,        18432, mb);
        bulkcp(sb+3*18432,  packB+4608,   18432, mb);
        uint32_t ina = sb + 18432*4;
        for(int r=0;r<64;r++) bulkcp(ina + r*544, in_g + r*128, 512, mb);
        bulkcp(sb + 27136*4,       isv? bv: bp,          512, mb);
        bulkcp(sb + 27136*4 + 512, g_biasF + isv*128,    512, mb);
    }

    float acc[16][4];
#pragma unroll
    for(int j=0;j<16;j++)
#pragma unroll
        for(int e=0;e<4;e++) acc[j][e]=0.f;

    mbwait(mb, 0);
    const float* r0 = in_s + (mbase+gid)*136 + 2*t4;
    const float* r1 = r0 + 8*136;

#pragma unroll
    for(int s=0;s<2;s++){
        unsigned ah[4][4];
        const int kb0 = s*64;
#pragma unroll
        for(int ks=0;ks<4;ks++){
            int ko = kb0 + ks*16;
            float2 a0=*(const float2*)&r0[ko],   c0=*(const float2*)&r1[ko];
            float2 a1=*(const float2*)&r0[ko+8], c1=*(const float2*)&r1[ko+8];
            ah[ks][0]=pk2(a0.x,a0.y);
            ah[ks][1]=pk2(c0.x,c0.y);
            ah[ks][2]=pk2(a1.x,a1.y);
            ah[ks][3]=pk2(c1.x,c1.y);
        }
        mmaW(acc, ah, Wres + pk*9216 + s*4608, lane);
    }

    float* outX = pk? outB: outA;
    float* o0 = outX + (size_t)(mbase+gid)*128;
    float* o1 = o0 + 8*128;
#pragma unroll
    for(int j=0;j<16;j++){
        int c=j*8+2*t4;
        float b0=bias_s[pk*128+c], b1=bias_s[pk*128+c+1];
        *(float2*)&o0[c] = make_float2(acc[j][0]+b0, acc[j][1]+b1);
        *(float2*)&o1[c] = make_float2(acc[j][2]+b0, acc[j][3]+b1);
    }
}

// A-fragment build (bases include +2*t4)
DI void buildA(unsigned ah[4][4], const float* pw, const float* v0, const float* v1, int s){
    const int kb0 = (s&1)*64;
    const float* pwk = pw + kb0;
    const float* v0k = v0 + kb0;
    const float* v1k = v1 + kb0;
#pragma unroll
    for(int ks=0;ks<4;ks++){
        int ko = ks*16;
        float2 pl = *(const float2*)&pwk[ko];
        float2 ph = *(const float2*)&pwk[ko+8];
        float2 a0=*(const float2*)&v0k[ko],   c0=*(const float2*)&v1k[ko];
        float2 a1=*(const float2*)&v0k[ko+8], c1=*(const float2*)&v1k[ko+8];
        if(s<2){
            ah[ks][0]=pk2(pl.x*a0.x, pl.y*a0.y);
            ah[ks][1]=pk2(pl.x*c0.x, pl.y*c0.y);
            ah[ks][2]=pk2(ph.x*a1.x, ph.y*a1.y);
            ah[ks][3]=pk2(ph.x*c1.x, ph.y*c1.y);
        }else{
            ah[ks][0]=pk2(fabsf(pl.x-a0.x), fabsf(pl.y-a0.y));
            ah[ks][1]=pk2(fabsf(pl.x-c0.x), fabsf(pl.y-c0.y));
            ah[ks][2]=pk2(fabsf(ph.x-a1.x), fabsf(ph.y-a1.y));
            ah[ks][3]=pk2(fabsf(ph.x-c1.x), fabsf(ph.y-c1.y));
        }
    }
}

DI void mmaH(float (*acc)[4], const unsigned h2[16][2], int s2, const unsigned* Wb, int lane){
#pragma unroll
    for(int ks=0;ks<4;ks++){
        int kg = s2*4+ks;
        const uint4* bb = (const uint4*)(Wb + (ks*32+lane)*36);
#pragma unroll
        for(int jj=0;jj<8;jj++){
            uint4 b = bb[jj];
            mma16(acc[2*jj],  h2[2*kg][0],h2[2*kg][1],h2[2*kg+1][0],h2[2*kg+1][1],b.x,b.y);
            mma16(acc[2*jj+1],h2[2*kg][0],h2[2*kg][1],h2[2*kg+1][0],h2[2*kg+1][1],b.z,b.w);
        }
    }
}

// ---------------------------------------------------------------------------
// pair_main (R14, 148us version — unchanged): 2048 x 256 thr, bulk loads,
// 4-slot W ring, batched-rcp SiLU. 113960 B smem -> 2 CTAs/SM.
// ---------------------------------------------------------------------------
__global__ __launch_bounds__(256,2) void pair_main_kernel(
    const float* __restrict__ b1v, const float* __restrict__ b2v,
    float* __restrict__ out){
    extern __shared__ float sm[];
    unsigned* Wbuf = (unsigned*)sm;
    float* b1_s = sm + 18432;
    float* b2_s = sm + 18560;
    float* v_s  = sm + 18688;
    float* V1_s = sm + 23040;
    float* p_s  = sm + 27392;
    float* P1_s = sm + 27936;
    const int bt=blockIdx.x>>3, pb=blockIdx.x&7;
    const int t=threadIdx.x, w=t>>5, lane=t&31;
    const int gid=lane>>2, t4=lane&3;
    const int n = w>>1, mbase = (w&1)*16;
    uint32_t Wba = s2u(Wbuf);
    uint32_t m0 = Wba + 28480*4;
    uint32_t m1 = m0+8, m2 = m0+16, m3 = m0+24, mt = m0+32;

    if(t==0){
        MBAR_INIT(m0,1); MBAR_INIT(m1,1); MBAR_INIT(m2,1);
        MBAR_INIT(m3,1); MBAR_INIT(mt,1);
    }
    __syncthreads();
    if(t==0){
        MBAR_EXPECT(m0,18432); bulkcp(Wba,         g_W1h,        18432, m0);
        MBAR_EXPECT(m1,18432); bulkcp(Wba+18432,   g_W1h+4608,   18432, m1);
        MBAR_EXPECT(m2,18432); bulkcp(Wba+2*18432, g_W1h+2*4608, 18432, m2);
        MBAR_EXPECT(m3,18432); bulkcp(Wba+3*18432, g_W1h+3*4608, 18432, m3);
        MBAR_EXPECT(mt, 32*512*2 + 4*512*2 + 1024);
        uint32_t vA = s2u(v_s), vB = s2u(V1_s), pA = s2u(p_s), pB = s2u(P1_s);
        const float* vg  = g_v  + (size_t)bt*4096;
        const float* V1g = g_V1 + (size_t)bt*4096;
        for(int m=0;m<32;m++){
            bulkcp(vA + m*544, vg  + m*128, 512, mt);
            bulkcp(vB + m*544, V1g + m*128, 512, mt);
        }
        const float* pg  = g_p  + (size_t)(bt*32+pb*4)*128;
        const float* P1g = g_P1 + (size_t)(bt*32+pb*4)*128;
        for(int nn=0;nn<4;nn++){
            bulkcp(pA + nn*544, pg  + nn*128, 512, mt);
            bulkcp(pB + nn*544, P1g + nn*128, 512, mt);
        }
        bulkcp(s2u(b1_s), b1v, 512, mt);
        bulkcp(s2u(b2_s), b2v, 512, mt);
    }

    float acc[16][4];
#pragma unroll
    for(int j=0;j<16;j++)
#pragma unroll
        for(int e=0;e<4;e++) acc[j][e]=0.f;

    mbwait(mt, 0);
    const float* pw = p_s + n*136 + 2*t4;
    const float* v0 = v_s + (mbase+gid)*136 + 2*t4;
    const float* v1 = v0 + 8*136;

    unsigned ah[4][4];
    buildA(ah, pw, v0, v1, 0);
    mbwait(m0, 0);
    mmaW(acc, ah, Wbuf, lane);
    buildA(ah, pw, v0, v1, 1);
    mbwait(m1, 0);
    mmaW(acc, ah, Wbuf+4608, lane);
    __syncthreads();
    if(t==0){
        MBAR_EXPECT(m0,18432); bulkcp(Wba,       g_W2h,      18432, m0);
        MBAR_EXPECT(m1,18432); bulkcp(Wba+18432, g_W2h+4608, 18432, m1);
    }
    buildA(ah, pw, v0, v1, 2);
    mbwait(m2, 0);
    mmaW(acc, ah, Wbuf+2*4608, lane);
    buildA(ah, pw, v0, v1, 3);
    mbwait(m3, 0);
    mmaW(acc, ah, Wbuf+3*4608, lane);

    // epilogue 1: silu via 4-way batched reciprocal
    unsigned h2[16][2];
#pragma unroll
    for(int j=0;j<16;j++){
        int c0=j*8+2*t4;
        float2 P  =*(const float2*)&P1_s[n*136+c0];
        float2 Bb =*(const float2*)&b1_s[c0];
        float2 V0 =*(const float2*)&V1_s[(mbase+gid)*136+c0];
        float2 V1r=*(const float2*)&V1_s[(mbase+gid+8)*136+c0];
        float x0=acc[j][0]+P.x+V0.x+Bb.x;
        float x1=acc[j][1]+P.y+V0.y+Bb.y;
        float x2=acc[j][2]+P.x+V1r.x+Bb.x;
        float x3=acc[j][3]+P.y+V1r.y+Bb.y;
        float u0=1.f+__expf(-x0), u1=1.f+__expf(-x1);
        float u2=1.f+__expf(-x2), u3=1.f+__expf(-x3);
        float p01=u0*u1, p23=u2*u3;
        float r = frcp(p01*p23);
        float r01 = r*p23, r23 = r*p01;
        x0 = x0*(r01*u1); x1 = x1*(r01*u0);
        x2 = x2*(r23*u3); x3 = x3*(r23*u2);
        h2[j][0]=pk2(x0,x1);
        h2[j][1]=pk2(x2,x3);
        acc[j][0]=0.f; acc[j][1]=0.f; acc[j][2]=0.f; acc[j][3]=0.f;
    }

    mbwait(m0, 1);
    mmaH(acc, h2, 0, Wbuf, lane);
    mbwait(m1, 1);
    mmaH(acc, h2, 1, Wbuf+4608, lane);

    const size_t ob = (size_t)blockIdx.x*16384;
    float* o0 = out + ob + (size_t)(w*16+gid)*128;
    float* o1 = o0 + 1024;
#pragma unroll
    for(int j=0;j<16;j++){
        int c=j*8+2*t4;
        *(float2*)&o0[c] = make_float2(acc[j][0]+b2_s[c], acc[j][1]+b2_s[c+1]);
        *(float2*)&o1[c] = make_float2(acc[j][2]+b2_s[c], acc[j][3]+b2_s[c+1]);
    }
}

extern "C" void kernel_launch(void* const* d_in, const int* in_sizes, int n_in,
                              void* d_out, int out_size){
    const float* price =(const float*)d_in[0];
    const float* liquid=(const float*)d_in[1];
    const float* W_p=(const float*)d_in[2];
    const float* b_p=(const float*)d_in[3];
    const float* W_v=(const float*)d_in[4];
    const float* b_v=(const float*)d_in[5];
    const float* W1 =(const float*)d_in[6];
    const float* b1 =(const float*)d_in[7];
    const float* W2 =(const float*)d_in[8];
    const float* b2 =(const float*)d_in[9];
    float* out=(float*)d_out;
    cudaFuncSetAttribute(pv_kernel, cudaFuncAttributeMaxDynamicSharedMemorySize, 110592);
    cudaFuncSetAttribute(pair_main_kernel, cudaFuncAttributeMaxDynamicSharedMemorySize, 114688);
    prep_kernel<<<16, 256>>>(W_p, b_p, W_v, b_v, W1);
    pack16_kernel<<<14, 128>>>(W1, W2, W_p, W_v);
    pv_kernel<<<256, 256, 109576>>>(price, liquid, b_p, b_v);
    pair_main_kernel<<<2048, 256, 113960>>>(b1, b2, out);
}